// round 9
// baseline (speedup 1.0000x reference)
#include <cuda_runtime.h>
#include <cuda_bf16.h>

// patches: [B=2, N=49, C=8, P=256, P=256] fp32; out: [B, C, 1024, 1024] fp32.
// Inverse-gather with branch-free clamped 4-tile loads, {0,1}-weighted FMA,
// out = sum / (count + 1e-8), count in {1,2,4}.
//
// Software-pipelined grid-stride: each thread issues the NEXT iteration's 8
// independent float4 loads before consuming the current iteration's, keeping
// loads in flight through the consume/store phase (continuous DRAM request
// stream). Reads are __ldcs (evict-first, use-once); stores are default
// write-back so L2 absorbs and schedules writebacks.

namespace {
constexpr int NB = 2;
constexpr int NN = 49;
constexpr int NC = 8;
constexpr int PP = 256;
constexpr int HH = 1024;
constexpr int WW = 1024;
constexpr int TILES = 7;

constexpr int TOTAL_F4    = NB * NC * HH * WW / 4;  // 4,194,304
constexpr int HALF_F4     = TOTAL_F4 / 2;           // 2,097,152 (8 bc-planes)
constexpr int CH_F4       = PP * PP / 4;            // 16,384
constexpr int BATCH_F4    = NN * NC * CH_F4;
constexpr int N_STRIDE_F4 = NC * CH_F4;
}

struct Offs {
    int s00, s01, s10, s11;   // within-plane f4 offsets of 4 candidate tiles
    int plane0;               // b=0 plane offset (b=1 = plane0 + BATCH_F4)
    float wc, wr;             // second col/row slot valid flags
};

__device__ __forceinline__ Offs calc_offs(int idx)
{
    Offs o;
    int w4 = idx & (WW / 4 - 1);
    int t  = idx >> 8;
    int h  = t & (HH - 1);
    int c  = t >> 10;
    int w  = w4 << 2;

    int thh = h >> 7, tww = w >> 7;
    int th0 = thh - 1 < 0 ? 0 : thh - 1;
    int th1 = thh > TILES - 1 ? TILES - 1 : thh;
    int tw0 = tww - 1 < 0 ? 0 : tww - 1;
    int tw1 = tww > TILES - 1 ? TILES - 1 : tww;

    o.wr = (th1 != th0) ? 1.f : 0.f;
    o.wc = (tw1 != tw0) ? 1.f : 0.f;

    int ph0 = h - (th0 << 7), ph1 = h - (th1 << 7);
    int pw0 = w - (tw0 << 7), pw1 = w - (tw1 << 7);

    o.s00 = (th0 * TILES + tw0) * N_STRIDE_F4 + ((ph0 * PP + pw0) >> 2);
    o.s01 = (th0 * TILES + tw1) * N_STRIDE_F4 + ((ph0 * PP + pw1) >> 2);
    o.s10 = (th1 * TILES + tw0) * N_STRIDE_F4 + ((ph1 * PP + pw0) >> 2);
    o.s11 = (th1 * TILES + tw1) * N_STRIDE_F4 + ((ph1 * PP + pw1) >> 2);
    o.plane0 = c * CH_F4;
    return o;
}

__device__ __forceinline__ void issue_loads(
    const float4* __restrict__ p4, const Offs& o, float4 v[8])
{
    v[0] = __ldcs(p4 + o.plane0 + o.s00);
    v[1] = __ldcs(p4 + o.plane0 + o.s01);
    v[2] = __ldcs(p4 + o.plane0 + o.s10);
    v[3] = __ldcs(p4 + o.plane0 + o.s11);
    v[4] = __ldcs(p4 + o.plane0 + BATCH_F4 + o.s00);
    v[5] = __ldcs(p4 + o.plane0 + BATCH_F4 + o.s01);
    v[6] = __ldcs(p4 + o.plane0 + BATCH_F4 + o.s10);
    v[7] = __ldcs(p4 + o.plane0 + BATCH_F4 + o.s11);
}

__device__ __forceinline__ void consume_store(
    float4* __restrict__ o4, const float4 v[8], const Offs& o, int idx)
{
    float w01 = o.wc, w10 = o.wr, w11 = o.wr * o.wc;
    float cnt = (1.f + o.wr) * (1.f + o.wc);        // exactly 1, 2, or 4
    float inv = 1.f / (cnt + 1e-8f);

    #pragma unroll
    for (int k = 0; k < 2; ++k) {
        const float4* b = &v[4 * k];
        float4 a;
        a.x = (b[0].x + w01 * b[1].x + w10 * b[2].x + w11 * b[3].x) * inv;
        a.y = (b[0].y + w01 * b[1].y + w10 * b[2].y + w11 * b[3].y) * inv;
        a.z = (b[0].z + w01 * b[1].z + w10 * b[2].z + w11 * b[3].z) * inv;
        a.w = (b[0].w + w01 * b[1].w + w10 * b[2].w + w11 * b[3].w) * inv;
        o4[idx + k * HALF_F4] = a;
    }
}

__global__ __launch_bounds__(256, 3) void patch_merge_pipe(
    const float* __restrict__ patches, float* __restrict__ out)
{
    const float4* __restrict__ p4 = reinterpret_cast<const float4*>(patches);
    float4* __restrict__ o4 = reinterpret_cast<float4*>(out);

    const int stride = gridDim.x * blockDim.x;
    int idx = blockIdx.x * blockDim.x + threadIdx.x;
    if (idx >= HALF_F4) return;

    // Prologue: stage current iteration's loads.
    Offs oc = calc_offs(idx);
    float4 vc[8];
    issue_loads(p4, oc, vc);

    for (;;) {
        int nidx = idx + stride;
        bool has_next = nidx < HALF_F4;

        Offs on;
        float4 vn[8];
        if (has_next) {
            on = calc_offs(nidx);
            issue_loads(p4, on, vn);      // next loads in flight...
        }

        consume_store(o4, vc, oc, idx);   // ...while current is consumed

        if (!has_next) break;
        idx = nidx;
        oc = on;
        #pragma unroll
        for (int i = 0; i < 8; ++i) vc[i] = vn[i];
    }
}

extern "C" void kernel_launch(void* const* d_in, const int* in_sizes, int n_in,
                              void* d_out, int out_size)
{
    const float* patches = (const float*)d_in[0];
    float* out = (float*)d_out;

    int dev = 0, sms = 148, maxBlk = 0;
    cudaGetDevice(&dev);
    cudaDeviceGetAttribute(&sms, cudaDevAttrMultiProcessorCount, dev);
    cudaOccupancyMaxActiveBlocksPerMultiprocessor(
        &maxBlk, patch_merge_pipe, 256, 0);
    if (maxBlk < 1) maxBlk = 3;
    int grid = sms * maxBlk;                 // single balanced wave
    int maxGrid = (HALF_F4 + 255) / 256;
    if (grid > maxGrid) grid = maxGrid;

    patch_merge_pipe<<<grid, 256>>>(patches, out);
}